// round 1
// baseline (speedup 1.0000x reference)
#include <cuda_runtime.h>
#include <cuda_bf16.h>

#define N_NODES 100000
#define DIM 64

// degree accumulator (scratch) — __device__ global, no allocations
__device__ float g_deg[N_NODES];

// ---------------------------------------------------------------------------
// Kernel 1: zero the aggregation buffer (d_out reused as agg) and degrees.
// ---------------------------------------------------------------------------
__global__ void zero_kernel(float* __restrict__ agg) {
    int stride = gridDim.x * blockDim.x;
    int i = blockIdx.x * blockDim.x + threadIdx.x;
    float4 z = make_float4(0.f, 0.f, 0.f, 0.f);
    const int n4 = (N_NODES * DIM) / 4;
    for (int idx = i; idx < n4; idx += stride)
        reinterpret_cast<float4*>(agg)[idx] = z;
    for (int idx = i; idx < N_NODES; idx += stride)
        g_deg[idx] = 0.f;
}

// ---------------------------------------------------------------------------
// Kernel 2: edge aggregation. 16 threads per edge, 4 features per thread.
// Gather x[src] (L2-resident) and red.global.add.v4.f32 into agg[dst].
// ---------------------------------------------------------------------------
__global__ void agg_kernel(const int* __restrict__ ei,
                           const float* __restrict__ x,
                           float* __restrict__ agg,
                           int E) {
    int idx = blockIdx.x * blockDim.x + threadIdx.x;   // < E*16 = 20M, fits int
    int e = idx >> 4;
    if (e >= E) return;
    int f = (idx & 15) * 4;
    int src = __ldg(ei + e);        // edge_index[0][e]
    int dst = __ldg(ei + E + e);    // edge_index[1][e]
    float4 v = *reinterpret_cast<const float4*>(x + (size_t)src * DIM + f);
    float* p = agg + (size_t)dst * DIM + f;
    asm volatile("red.global.add.v4.f32 [%0], {%1,%2,%3,%4};"
                 :: "l"(p), "f"(v.x), "f"(v.y), "f"(v.z), "f"(v.w)
                 : "memory");
    if ((idx & 15) == 0)
        atomicAdd(g_deg + dst, 1.0f);
}

// ---------------------------------------------------------------------------
// Kernel 3: out = relu(x @ Ws^T + b + (agg/deg) @ Wn^T), in-place over agg.
// Persistent grid. Warp handles 2 nodes; lane j computes outputs j and j+32.
// Weights staged in shared, transposed + interleaved: Wp[k*64+j] = (Ws[j][k], Wn[j][k]).
// ---------------------------------------------------------------------------
__global__ void __launch_bounds__(256, 4)
gcn_out_kernel(const float* __restrict__ x,
               const float* __restrict__ Wself,
               const float* __restrict__ bself,
               const float* __restrict__ Wneigh,
               float* __restrict__ out /* = agg on input */) {
    __shared__ float2 Wp[64 * 64];
    int tid = threadIdx.x;
    for (int idx = tid; idx < 4096; idx += blockDim.x) {
        int k = idx >> 6, j = idx & 63;
        Wp[idx] = make_float2(Wself[j * 64 + k], Wneigh[j * 64 + k]);
    }
    __syncthreads();

    int lane = tid & 31;
    int warp = tid >> 5;
    int gw = blockIdx.x * (blockDim.x >> 5) + warp;
    int nwarps = gridDim.x * (blockDim.x >> 5);
    const float bj   = __ldg(bself + lane);
    const float bj32 = __ldg(bself + 32 + lane);
    const int npairs = N_NODES / 2;   // N even

    for (int p = gw; p < npairs; p += nwarps) {
        int n0 = 2 * p, n1 = 2 * p + 1;
        float inv0 = 1.f / fmaxf(g_deg[n0], 1.f);
        float inv1 = 1.f / fmaxf(g_deg[n1], 1.f);
        const float* x0 = x + (size_t)n0 * 64;
        const float* x1 = x + (size_t)n1 * 64;
        float* a0 = out + (size_t)n0 * 64;
        float* a1 = out + (size_t)n1 * 64;

        float xa0 = x0[lane], xb0 = x0[32 + lane];
        float xa1 = x1[lane], xb1 = x1[32 + lane];
        float ma0 = a0[lane] * inv0, mb0 = a0[32 + lane] * inv0;
        float ma1 = a1[lane] * inv1, mb1 = a1[32 + lane] * inv1;

        float acc00 = 0.f, acc01 = 0.f, acc10 = 0.f, acc11 = 0.f;

        #pragma unroll
        for (int k = 0; k < 32; k++) {
            float xs0 = __shfl_sync(0xffffffffu, xa0, k);
            float ms0 = __shfl_sync(0xffffffffu, ma0, k);
            float xs1 = __shfl_sync(0xffffffffu, xa1, k);
            float ms1 = __shfl_sync(0xffffffffu, ma1, k);
            float2 wlo = Wp[k * 64 + lane];
            float2 whi = Wp[k * 64 + 32 + lane];
            acc00 += xs0 * wlo.x; acc00 += ms0 * wlo.y;
            acc01 += xs0 * whi.x; acc01 += ms0 * whi.y;
            acc10 += xs1 * wlo.x; acc10 += ms1 * wlo.y;
            acc11 += xs1 * whi.x; acc11 += ms1 * whi.y;
        }
        #pragma unroll
        for (int k = 0; k < 32; k++) {
            float xs0 = __shfl_sync(0xffffffffu, xb0, k);
            float ms0 = __shfl_sync(0xffffffffu, mb0, k);
            float xs1 = __shfl_sync(0xffffffffu, xb1, k);
            float ms1 = __shfl_sync(0xffffffffu, mb1, k);
            float2 wlo = Wp[(32 + k) * 64 + lane];
            float2 whi = Wp[(32 + k) * 64 + 32 + lane];
            acc00 += xs0 * wlo.x; acc00 += ms0 * wlo.y;
            acc01 += xs0 * whi.x; acc01 += ms0 * whi.y;
            acc10 += xs1 * wlo.x; acc10 += ms1 * wlo.y;
            acc11 += xs1 * whi.x; acc11 += ms1 * whi.y;
        }

        __syncwarp();   // all reads of a0/a1 done before in-place writes
        a0[lane]      = fmaxf(acc00 + bj,   0.f);
        a0[32 + lane] = fmaxf(acc01 + bj32, 0.f);
        a1[lane]      = fmaxf(acc10 + bj,   0.f);
        a1[32 + lane] = fmaxf(acc11 + bj32, 0.f);
    }
}

// ---------------------------------------------------------------------------
extern "C" void kernel_launch(void* const* d_in, const int* in_sizes, int n_in,
                              void* d_out, int out_size) {
    const float* x  = (const float*)d_in[0];
    const int*   ei = (const int*)  d_in[1];
    const float* Ws = (const float*)d_in[2];
    const float* bs = (const float*)d_in[3];
    const float* Wn = (const float*)d_in[4];
    float* out = (float*)d_out;
    int E = in_sizes[1] / 2;

    zero_kernel<<<592, 256>>>(out);

    int total = E * 16;
    agg_kernel<<<(total + 255) / 256, 256>>>(ei, x, out, E);

    gcn_out_kernel<<<592, 256>>>(x, Ws, bs, Wn, out);
}

// round 2
// speedup vs baseline: 1.4645x; 1.4645x over previous
#include <cuda_runtime.h>
#include <cuda_bf16.h>

#define NN 100000
#define NE 1250000
#define DIM 64
#define SCAN_VPB 1024                  // values per scan block
#define SCAN_NB  ((NN + SCAN_VPB - 1) / SCAN_VPB)   // 98

// ---- static device scratch (no allocations allowed) ----
__device__ int g_cnt[NN];        // histogram, then scatter cursor
__device__ int g_start[NN];      // exclusive CSR offsets
__device__ int g_blk[256];       // scan block sums
__device__ int g_src[NE];        // edge srcs sorted by dst

// ---------------------------------------------------------------------------
// f32x2 packed-FMA helpers (sm_103a; ptxas never auto-fuses these)
// ---------------------------------------------------------------------------
__device__ __forceinline__ void ffma2(unsigned long long& d,
                                      unsigned long long a,
                                      unsigned long long b) {
    asm("fma.rn.f32x2 %0, %1, %2, %0;" : "+l"(d) : "l"(a), "l"(b));
}
__device__ __forceinline__ unsigned long long pk(float x, float y) {
    unsigned long long r;
    asm("mov.b64 %0, {%1, %2};" : "=l"(r) : "f"(x), "f"(y));
    return r;
}
__device__ __forceinline__ float2 unpk(unsigned long long v) {
    float2 r;
    asm("mov.b64 {%0, %1}, %2;" : "=f"(r.x), "=f"(r.y) : "l"(v));
    return r;
}

// ---------------------------------------------------------------------------
// CSR build
// ---------------------------------------------------------------------------
__global__ void k_zero_cnt() {
    int i = blockIdx.x * blockDim.x + threadIdx.x;
    if (i < NN) g_cnt[i] = 0;
}

__global__ void k_hist(const int* __restrict__ ei, int E) {
    int e = blockIdx.x * blockDim.x + threadIdx.x;
    if (e < E) atomicAdd(&g_cnt[__ldg(ei + E + e)], 1);
}

// per-block exclusive scan (256 thr x 4 vals), block totals to g_blk
__global__ void k_scan1() {
    __shared__ int wsum[8];
    int t = threadIdx.x, b = blockIdx.x;
    int base = b * SCAN_VPB + t * 4;
    int c0 = (base + 0 < NN) ? g_cnt[base + 0] : 0;
    int c1 = (base + 1 < NN) ? g_cnt[base + 1] : 0;
    int c2 = (base + 2 < NN) ? g_cnt[base + 2] : 0;
    int c3 = (base + 3 < NN) ? g_cnt[base + 3] : 0;
    int tot = c0 + c1 + c2 + c3;

    int lane = t & 31, w = t >> 5;
    int inc = tot;
    #pragma unroll
    for (int d = 1; d < 32; d <<= 1) {
        int v = __shfl_up_sync(0xffffffffu, inc, d);
        if (lane >= d) inc += v;
    }
    if (lane == 31) wsum[w] = inc;
    __syncthreads();
    if (t == 0) {
        int acc = 0;
        #pragma unroll
        for (int i = 0; i < 8; i++) { int v = wsum[i]; wsum[i] = acc; acc += v; }
    }
    __syncthreads();
    int excl = wsum[w] + inc - tot;   // exclusive within block
    if (base + 0 < NN) g_start[base + 0] = excl;
    if (base + 1 < NN) g_start[base + 1] = excl + c0;
    if (base + 2 < NN) g_start[base + 2] = excl + c0 + c1;
    if (base + 3 < NN) g_start[base + 3] = excl + c0 + c1 + c2;
    if (t == 255) g_blk[b] = excl + tot;   // block total
}

// exclusive scan of SCAN_NB block totals (one block, 128 threads)
__global__ void k_scan2() {
    __shared__ int wsum[4];
    int t = threadIdx.x;
    int v = (t < SCAN_NB) ? g_blk[t] : 0;
    int lane = t & 31, w = t >> 5;
    int inc = v;
    #pragma unroll
    for (int d = 1; d < 32; d <<= 1) {
        int u = __shfl_up_sync(0xffffffffu, inc, d);
        if (lane >= d) inc += u;
    }
    if (lane == 31) wsum[w] = inc;
    __syncthreads();
    if (t == 0) {
        int acc = 0;
        #pragma unroll
        for (int i = 0; i < 4; i++) { int u = wsum[i]; wsum[i] = acc; acc += u; }
    }
    __syncthreads();
    if (t < SCAN_NB) g_blk[t] = wsum[w] + inc - v;   // exclusive
}

// add block offsets; init scatter cursor
__global__ void k_scan3() {
    int i = blockIdx.x * blockDim.x + threadIdx.x;
    if (i < NN) {
        int s = g_start[i] + g_blk[i / SCAN_VPB];
        g_start[i] = s;
        g_cnt[i] = s;
    }
}

__global__ void k_scatter(const int* __restrict__ ei, int E) {
    int e = blockIdx.x * blockDim.x + threadIdx.x;
    if (e < E) {
        int dst = __ldg(ei + E + e);
        int pos = atomicAdd(&g_cnt[dst], 1);
        g_src[pos] = __ldg(ei + e);
    }
}

// ---------------------------------------------------------------------------
// Fused: per-node neighbor-mean gather + dual matvec (FFMA2) + bias + ReLU.
// Warp handles 4 nodes. Concat vector a[0..63]=x_row, a[64..127]=mean.
// W'[k][j] = k<64 ? Ws[j][k] : Wn[j][k-64].
// Wa[k2][j] = (W'[2k2][j], W'[2k2+1][j])  -- K-packed pairs for f32x2.
// acc2 holds (sum over even k, sum over odd k); epilogue adds halves.
// ---------------------------------------------------------------------------
__global__ void __launch_bounds__(256, 4)
k_fused(const float* __restrict__ x,
        const float* __restrict__ Ws,
        const float* __restrict__ bs,
        const float* __restrict__ Wn,
        float* __restrict__ out,
        int E) {
    __shared__ float2 Wa[64][64];     // 32 KB
    __shared__ float  As[8][4][128];  // 16 KB  (per-warp a-staging)

    int tid = threadIdx.x;
    for (int idx = tid; idx < 4096; idx += 256) {
        int k2 = idx >> 6, j = idx & 63;
        int k0 = 2 * k2, k1 = 2 * k2 + 1;
        float w0 = (k0 < 64) ? Ws[j * 64 + k0] : Wn[j * 64 + (k0 - 64)];
        float w1 = (k1 < 64) ? Ws[j * 64 + k1] : Wn[j * 64 + (k1 - 64)];
        Wa[k2][j] = make_float2(w0, w1);
    }
    __syncthreads();

    int lane = tid & 31, warp = tid >> 5;
    const float b0 = __ldg(bs + lane);
    const float b1 = __ldg(bs + 32 + lane);
    const float2* xp = (const float2*)x;
    const int ngroups = NN / 4;     // 25000, NN divisible by 4

    for (int g = blockIdx.x * 8 + warp; g < ngroups; g += gridDim.x * 8) {
        int n0 = g * 4;
        float* as = &As[warp][0][0];

        // ---- gather + stage 4 nodes ----
        #pragma unroll
        for (int nn = 0; nn < 4; nn++) {
            int n = n0 + nn;
            int e0 = __ldg(&g_start[n]);
            int e1 = (n == NN - 1) ? E : __ldg(&g_start[n + 1]);
            float ax = 0.f, ay = 0.f;
            int e = e0;
            for (; e + 4 <= e1; e += 4) {
                int s0 = __ldg(g_src + e);
                int s1 = __ldg(g_src + e + 1);
                int s2 = __ldg(g_src + e + 2);
                int s3 = __ldg(g_src + e + 3);
                float2 v0 = __ldg(xp + s0 * 32 + lane);
                float2 v1 = __ldg(xp + s1 * 32 + lane);
                float2 v2 = __ldg(xp + s2 * 32 + lane);
                float2 v3 = __ldg(xp + s3 * 32 + lane);
                ax += (v0.x + v1.x) + (v2.x + v3.x);
                ay += (v0.y + v1.y) + (v2.y + v3.y);
            }
            for (; e < e1; e++) {
                int s = __ldg(g_src + e);
                float2 v = __ldg(xp + s * 32 + lane);
                ax += v.x; ay += v.y;
            }
            float inv = 1.f / fmaxf((float)(e1 - e0), 1.f);
            float2 xs = __ldg(xp + n * 32 + lane);
            ((float2*)(as + nn * 128))[lane]      = xs;                         // k = 2*lane
            ((float2*)(as + nn * 128 + 64))[lane] = make_float2(ax * inv, ay * inv);
        }
        __syncwarp();

        // ---- dual matvec, K-packed f32x2 ----
        unsigned long long acc[4][2];
        #pragma unroll
        for (int nn = 0; nn < 4; nn++) { acc[nn][0] = 0ull; acc[nn][1] = 0ull; }

        #pragma unroll 8
        for (int k4 = 0; k4 < 32; k4++) {
            unsigned long long wa0 = *(const unsigned long long*)&Wa[2 * k4][lane];
            unsigned long long wb0 = *(const unsigned long long*)&Wa[2 * k4][lane + 32];
            unsigned long long wa1 = *(const unsigned long long*)&Wa[2 * k4 + 1][lane];
            unsigned long long wb1 = *(const unsigned long long*)&Wa[2 * k4 + 1][lane + 32];
            #pragma unroll
            for (int nn = 0; nn < 4; nn++) {
                float4 a = *(const float4*)(as + nn * 128 + 4 * k4);   // broadcast
                unsigned long long a01 = pk(a.x, a.y);
                unsigned long long a23 = pk(a.z, a.w);
                ffma2(acc[nn][0], a01, wa0);
                ffma2(acc[nn][1], a01, wb0);
                ffma2(acc[nn][0], a23, wa1);
                ffma2(acc[nn][1], a23, wb1);
            }
        }

        // ---- epilogue: sum halves, bias, relu, store ----
        #pragma unroll
        for (int nn = 0; nn < 4; nn++) {
            float2 lo = unpk(acc[nn][0]);
            float2 hi = unpk(acc[nn][1]);
            float o0 = fmaxf(lo.x + lo.y + b0, 0.f);
            float o1 = fmaxf(hi.x + hi.y + b1, 0.f);
            float* orow = out + (size_t)(n0 + nn) * 64;
            orow[lane]      = o0;
            orow[32 + lane] = o1;
        }
        __syncwarp();   // staging reuse next iteration
    }
}

// ---------------------------------------------------------------------------
extern "C" void kernel_launch(void* const* d_in, const int* in_sizes, int n_in,
                              void* d_out, int out_size) {
    const float* x  = (const float*)d_in[0];
    const int*   ei = (const int*)  d_in[1];
    const float* Ws = (const float*)d_in[2];
    const float* bs = (const float*)d_in[3];
    const float* Wn = (const float*)d_in[4];
    float* out = (float*)d_out;
    int E = in_sizes[1] / 2;

    k_zero_cnt<<<(NN + 255) / 256, 256>>>();
    k_hist<<<(E + 255) / 256, 256>>>(ei, E);
    k_scan1<<<SCAN_NB, 256>>>();
    k_scan2<<<1, 128>>>();
    k_scan3<<<(NN + 255) / 256, 256>>>();
    k_scatter<<<(E + 255) / 256, 256>>>(ei, E);
    k_fused<<<592, 256>>>(x, Ws, bs, Wn, out, E);
}